// round 2
// baseline (speedup 1.0000x reference)
#include <cuda_runtime.h>
#include <math.h>

#define IN_DIM   256
#define OUT_DIM  512
#define MEM_LEN  131072
#define BETA     1.0f

// Scratch (no allocations allowed)
__device__ float g_enc[OUT_DIM];
__device__ float g_dists[MEM_LEN];

// ---------------------------------------------------------------------------
// Kernel A: xnorm -> dense encoder -> log_softmax -> g_enc. 1 block, 128 thr.
// Each thread owns 4 output columns via float4 loads of W (coalesced 512B/warp).
// ---------------------------------------------------------------------------
__global__ void enc_kernel(const float* __restrict__ x,
                           const float* __restrict__ W,
                           const float* __restrict__ b,
                           const float* __restrict__ mean,
                           const float* __restrict__ stdv) {
    __shared__ float xn[IN_DIM];
    __shared__ float redm[4];
    __shared__ float reds[4];
    int t = threadIdx.x;                 // 0..127
    for (int i = t; i < IN_DIM; i += 128) {
        float s = stdv[i];
        xn[i] = (s == 0.0f) ? 0.0f : (x[i] - mean[i]) / s;
    }
    __syncthreads();

    const float4* W4 = (const float4*)W;     // (256, 512) row-major -> 128 float4 per row
    float4 acc = make_float4(0.f, 0.f, 0.f, 0.f);
#pragma unroll 8
    for (int i = 0; i < IN_DIM; i++) {
        float  xi = xn[i];
        float4 w  = __ldg(&W4[i * (OUT_DIM / 4) + t]);
        acc.x = fmaf(xi, w.x, acc.x);
        acc.y = fmaf(xi, w.y, acc.y);
        acc.z = fmaf(xi, w.z, acc.z);
        acc.w = fmaf(xi, w.w, acc.w);
    }
    float4 bb = __ldg(&((const float4*)b)[t]);
    acc.x += bb.x; acc.y += bb.y; acc.z += bb.z; acc.w += bb.w;

    // logsumexp over all 512 values
    float m = fmaxf(fmaxf(acc.x, acc.y), fmaxf(acc.z, acc.w));
#pragma unroll
    for (int o = 16; o; o >>= 1) m = fmaxf(m, __shfl_xor_sync(0xffffffffu, m, o));
    if ((t & 31) == 0) redm[t >> 5] = m;
    __syncthreads();
    m = fmaxf(fmaxf(redm[0], redm[1]), fmaxf(redm[2], redm[3]));

    float s = expf(acc.x - m) + expf(acc.y - m) + expf(acc.z - m) + expf(acc.w - m);
#pragma unroll
    for (int o = 16; o; o >>= 1) s += __shfl_xor_sync(0xffffffffu, s, o);
    if ((t & 31) == 0) reds[t >> 5] = s;
    __syncthreads();
    s = reds[0] + reds[1] + reds[2] + reds[3];

    float lse = m + logf(s);
    float4 e = make_float4(acc.x - lse, acc.y - lse, acc.z - lse, acc.w - lse);
    ((float4*)g_enc)[t] = e;
}

// ---------------------------------------------------------------------------
// Kernel B: per-row L1 distance to g_enc fused with copy memory -> out+1.
// Destination is misaligned by 1 float, so thread t (t<127) covers the
// shifted window k = 4t+3 .. 4t+6 (dst index = 512*row + 4t + 4, 16B aligned)
// with 4 scalar LDG + 1 STG.128. Thread 127 mops up k in {0,1,2,511}.
// ---------------------------------------------------------------------------
__global__ void dist_copy_kernel(const float* __restrict__ memory,
                                 float* __restrict__ out) {
    __shared__ float red[4];
    int row = blockIdx.x;
    int t   = threadIdx.x;               // 0..127
    const float* mrow = memory + (size_t)row * OUT_DIM;
    float*       orow = out + 1 + (size_t)row * OUT_DIM;

    float part;
    if (t < 127) {
        int k = 4 * t + 3;
        float a0 = __ldg(mrow + k + 0);
        float a1 = __ldg(mrow + k + 1);
        float a2 = __ldg(mrow + k + 2);
        float a3 = __ldg(mrow + k + 3);
        part = fabsf(a0 - g_enc[k + 0]) + fabsf(a1 - g_enc[k + 1])
             + fabsf(a2 - g_enc[k + 2]) + fabsf(a3 - g_enc[k + 3]);
        *(float4*)(orow + k) = make_float4(a0, a1, a2, a3);
    } else {
        float a3 = __ldg(mrow + 511);
        float a0 = __ldg(mrow + 0);
        float a1 = __ldg(mrow + 1);
        float a2 = __ldg(mrow + 2);
        part = fabsf(a3 - g_enc[511]) + fabsf(a0 - g_enc[0])
             + fabsf(a1 - g_enc[1])   + fabsf(a2 - g_enc[2]);
        orow[511] = a3; orow[0] = a0; orow[1] = a1; orow[2] = a2;
    }

#pragma unroll
    for (int o = 16; o; o >>= 1) part += __shfl_xor_sync(0xffffffffu, part, o);
    if ((t & 31) == 0) red[t >> 5] = part;
    __syncthreads();
    if (t == 0) g_dists[row] = red[0] + red[1] + red[2] + red[3];
}

// ---------------------------------------------------------------------------
// Kernel C: copy mem_data (33.5M floats) to out + 1 + MEM_LEN*OUT_DIM with the
// same shifted-vector store trick. NV full float4 stores + 4 leftover scalars.
// ---------------------------------------------------------------------------
#define CPY_N   ((long long)MEM_LEN * IN_DIM)      // 33554432
#define CPY_NV  ((CPY_N - 4) / 4)                  // 8388607 vec stores at j=4v+3

__global__ void memdata_copy_kernel(const float* __restrict__ src,
                                    float* __restrict__ out) {
    float* dst = out + 1 + (size_t)MEM_LEN * OUT_DIM;
    long long gid = (long long)blockIdx.x * blockDim.x + threadIdx.x;
    if (gid < CPY_NV) {
        long long j = 4 * gid + 3;
        float a0 = __ldg(src + j + 0);
        float a1 = __ldg(src + j + 1);
        float a2 = __ldg(src + j + 2);
        float a3 = __ldg(src + j + 3);
        *(float4*)(dst + j) = make_float4(a0, a1, a2, a3);
    } else if (gid == CPY_NV) {
        dst[0] = __ldg(src + 0);
        dst[1] = __ldg(src + 1);
        dst[2] = __ldg(src + 2);
        dst[CPY_N - 1] = __ldg(src + CPY_N - 1);
    }
}

// ---------------------------------------------------------------------------
// Kernel D: min-reduce g_dists -> loss; conditional slot overwrite.
// ---------------------------------------------------------------------------
__global__ void finalize_kernel(const float* __restrict__ x,
                                const int* __restrict__ countp,
                                float* __restrict__ out) {
    __shared__ float red[32];
    __shared__ float s_loss;
    int t = threadIdx.x;                 // 0..1023
    float m = INFINITY;
    const float4* d4 = (const float4*)g_dists;
    for (int i = t; i < MEM_LEN / 4; i += 1024) {
        float4 v = d4[i];
        m = fminf(m, fminf(fminf(v.x, v.y), fminf(v.z, v.w)));
    }
#pragma unroll
    for (int o = 16; o; o >>= 1) m = fminf(m, __shfl_xor_sync(0xffffffffu, m, o));
    if ((t & 31) == 0) red[t >> 5] = m;
    __syncthreads();
    if (t < 32) {
        float mm = red[t];
#pragma unroll
        for (int o = 16; o; o >>= 1) mm = fminf(mm, __shfl_xor_sync(0xffffffffu, mm, o));
        if (t == 0) { out[0] = mm; s_loss = mm; }
    }
    __syncthreads();

    if (s_loss <= BETA) {
        int count = countp ? countp[0] : 5;
        int pos = count % MEM_LEN;
        if (pos < 0) pos += MEM_LEN;
        if (t < OUT_DIM)
            out[1 + (size_t)pos * OUT_DIM + t] = g_enc[t];
        if (t < IN_DIM)
            out[1 + (size_t)MEM_LEN * OUT_DIM + (size_t)pos * IN_DIM + t] = x[t];
    }
}

// ---------------------------------------------------------------------------
extern "C" void kernel_launch(void* const* d_in, const int* in_sizes, int n_in,
                              void* d_out, int out_size) {
    const float* x        = (const float*)d_in[0];
    const float* W_enc    = (const float*)d_in[1];
    const float* b_enc    = (const float*)d_in[2];
    const float* memory   = (const float*)d_in[3];
    const float* mem_data = (const float*)d_in[4];
    const float* mean     = (const float*)d_in[5];
    const float* stdv     = (const float*)d_in[6];
    const int*   countp   = (n_in > 7) ? (const int*)d_in[7] : nullptr;
    float* out = (float*)d_out;

    enc_kernel<<<1, 128>>>(x, W_enc, b_enc, mean, stdv);
    dist_copy_kernel<<<MEM_LEN, 128>>>(memory, out);
    {
        long long total = CPY_NV + 1;
        int threads = 256;
        int blocks = (int)((total + threads - 1) / threads);
        memdata_copy_kernel<<<blocks, threads>>>(mem_data, out);
    }
    finalize_kernel<<<1, 1024>>>(x, countp, out);
}